// round 2
// baseline (speedup 1.0000x reference)
#include <cuda_runtime.h>

// ============================================================================
// EstimateCentroids: 9^3 binary erosion (separable, bit-packed) -> hash-binned
// integer segment sums (packed u64 shared atomics, persistent blocks) ->
// centroids/boxes -> fused stable rank sort+scatter -> direct greedy NMS.
// ============================================================================

#define XD 512
#define YD 512
#define ZD 48
#define NROWS (XD * YD)              // 262144
#define NVOX  (NROWS * ZD)           // 12582912
#define NBINS 4096
#define NWORDS 64                    // 4096/64

// ---------------- device scratch (static: no allocations allowed) -----------
__device__ unsigned long long g_zbits[NROWS];
__device__ unsigned long long g_xbits[NROWS];
__device__ unsigned long long g_acc1[NBINS];   // (sx+256c)<<32 | (sy+256c)
__device__ unsigned long long g_acc2[NBINS];   // (sz+256c)<<32 | c
__device__ float4 g_boxes[NBINS];
__device__ float4 g_bsort[NBINS];
__device__ int    g_scores[NBINS];
__device__ int    g_order[NBINS];
__device__ unsigned long long g_clusterbits[NWORDS];

// ---------------- erosion along z (and binarize) + zero accumulators --------
// Block = 384 threads = 8 rows of 48 z-values, fully coalesced loads.
__global__ void erode_z_kernel(const float* __restrict__ pm) {
    __shared__ unsigned int bal[12];
    int tid = threadIdx.x;
    int gidx = blockIdx.x * 384 + tid;
    // fused zeroing of the tiny accumulator arrays
    if (gidx < NBINS) { g_acc1[gidx] = 0ULL; g_acc2[gidx] = 0ULL; }
    if (gidx < NWORDS) g_clusterbits[gidx] = 0ULL;

    float v = pm[gidx];
    unsigned int m = __ballot_sync(0xFFFFFFFFu, v > 0.5f);
    if ((tid & 31) == 0) bal[tid >> 5] = m;
    __syncthreads();
    if (tid < 8) {
        const unsigned char* by = (const unsigned char*)bal;
        unsigned long long b = 0ULL;
        #pragma unroll
        for (int k = 0; k < 6; k++)
            b |= (unsigned long long)by[tid * 6 + k] << (8 * k);
        unsigned long long e = b;
        #pragma unroll
        for (int k = 1; k <= 4; k++)
            e &= (b >> k) & (b << k);
        e &= 0x0000FFFFFFFFFFFFULL;
        g_zbits[blockIdx.x * 8 + tid] = e;
    }
}

// ---------------- fused erosion along y then x (shared tile) -----------------
// Tile: 32x32 output rows, 4-halo each side.
__global__ void erode_yx_kernel() {
    __shared__ unsigned long long sz[40][40];   // [x][y] with halo
    __shared__ unsigned long long sy[40][32];   // y-eroded, x-halo retained
    int tid = threadIdx.x;
    int x0 = blockIdx.x * 32, y0 = blockIdx.y * 32;

    for (int l = tid; l < 40 * 40; l += 256) {
        int xx = l / 40, yy = l - xx * 40;
        int gx = x0 + xx - 4, gy = y0 + yy - 4;
        unsigned long long v = 0ULL;
        if (gx >= 0 && gx < XD && gy >= 0 && gy < YD)
            v = g_zbits[gx * YD + gy];
        sz[xx][yy] = v;
    }
    __syncthreads();

    for (int l = tid; l < 40 * 32; l += 256) {
        int xx = l >> 5, yy = l & 31;
        int gy = y0 + yy;
        unsigned long long r = 0ULL;
        if (gy >= 4 && gy <= YD - 5) {
            r = ~0ULL;
            #pragma unroll
            for (int dy = 0; dy <= 8; dy++)
                r &= sz[xx][yy + dy];
        }
        sy[xx][yy] = r;
    }
    __syncthreads();

    for (int l = tid; l < 32 * 32; l += 256) {
        int xx = l >> 5, yy = l & 31;
        int gx = x0 + xx;
        unsigned long long r = 0ULL;
        if (gx >= 4 && gx <= XD - 5) {
            r = ~0ULL;
            #pragma unroll
            for (int dx = 0; dx <= 8; dx++)
                r &= sy[xx + dx][yy];
        }
        g_xbits[gx * YD + (y0 + yy)] = r;
    }
}

// ---------------- main accumulation -----------------------------------------
// Row-per-thread, float4 loads, one packed u64 shared atomic per valid voxel:
//   bits[48:64) = count(+1), [32:48) = x+256, [16:32) = y+256, [0:16) = z+256
// Persistent grid (2 blocks/SM) so the global flush is only 296*8192 lanes.
#define ACC_BLOCKS 296
#define ACC_THREADS 256
__global__ void __launch_bounds__(ACC_THREADS) accum_kernel(const float* __restrict__ emb) {
    __shared__ unsigned long long sbins[NBINS];
    for (int i = threadIdx.x; i < NBINS; i += ACC_THREADS) sbins[i] = 0ULL;
    __syncthreads();

    const float* __restrict__ e0 = emb;
    const float* __restrict__ e1 = emb + NVOX;
    const float* __restrict__ e2 = emb + 2 * NVOX;

    int stride = ACC_BLOCKS * ACC_THREADS;
    for (int row = blockIdx.x * ACC_THREADS + threadIdx.x; row < NROWS; row += stride) {
        unsigned long long mask = g_xbits[row];
        if (!mask) continue;
        const float4* p0 = (const float4*)(e0 + row * 48);
        const float4* p1 = (const float4*)(e1 + row * 48);
        const float4* p2 = (const float4*)(e2 + row * 48);
        #pragma unroll 4
        for (int c = 0; c < 12; c++) {
            unsigned int m4 = (unsigned int)(mask >> (c * 4)) & 0xFu;
            if (!m4) continue;
            float4 fa = p0[c], fb = p1[c], fc = p2[c];
            float ax[4] = {fa.x, fa.y, fa.z, fa.w};
            float bx[4] = {fb.x, fb.y, fb.z, fb.w};
            float cx4[4] = {fc.x, fc.y, fc.z, fc.w};
            #pragma unroll
            for (int k = 0; k < 4; k++) {
                if (!((m4 >> k) & 1u)) continue;
                float a = ax[k], b = bx[k], c2 = cx4[k];
                if (a > -2.0f || b > -2.0f || c2 > -2.0f) {
                    int cx = __float2int_rn(a * 25.0f);   // round-half-even
                    int cy = __float2int_rn(b * 25.0f);
                    int cz = __float2int_rn(c2 * 25.0f);
                    unsigned int qx = (unsigned int)min(max(cx + 128, 0), 255);
                    unsigned int qy = (unsigned int)min(max(cy + 128, 0), 255);
                    unsigned int qz = (unsigned int)min(max(cz + 128, 0), 255);
                    unsigned int h = qx * 73856093u ^ qy * 19349663u ^ qz * 83492791u;
                    unsigned int seg = h & (NBINS - 1);
                    unsigned long long p =
                        (1ULL << 48) |
                        ((unsigned long long)(unsigned int)(cx + 256) << 32) |
                        ((unsigned long long)(unsigned int)(cy + 256) << 16) |
                        (unsigned long long)(unsigned int)(cz + 256);
                    atomicAdd(&sbins[seg], p);
                }
            }
        }
    }
    __syncthreads();

    for (int i = threadIdx.x; i < NBINS; i += ACC_THREADS) {
        unsigned long long p = sbins[i];
        if (p) {
            unsigned long long cnt = p >> 48;
            unsigned long long xf = (p >> 32) & 0xFFFFULL;
            unsigned long long yf = (p >> 16) & 0xFFFFULL;
            unsigned long long zf = p & 0xFFFFULL;
            atomicAdd(&g_acc1[i], (xf << 32) | yf);
            atomicAdd(&g_acc2[i], (zf << 32) | cnt);
        }
    }
}

// ---------------- finalize: centroids, boxes, scores ------------------------
__global__ void finalize_kernel(float* __restrict__ out, int out_size) {
    int i = blockIdx.x * blockDim.x + threadIdx.x;
    if (i >= NBINS) return;
    unsigned long long a1 = g_acc1[i];
    unsigned long long a2 = g_acc2[i];
    int cnt = (int)(a2 & 0xFFFFFFFFULL);
    int sx = (int)(a1 >> 32) - 256 * cnt;
    int sy = (int)(a1 & 0xFFFFFFFFULL) - 256 * cnt;
    int sz = (int)(a2 >> 32) - 256 * cnt;
    float d = fmaxf((float)cnt, 1.0f);
    float c0 = (float)sx / d;
    float c1 = (float)sy / d;
    float c2 = (float)sz / d;
    if (i * 3 + 2 < out_size) {
        out[i * 3 + 0] = c0;
        out[i * 3 + 1] = c1;
        out[i * 3 + 2] = c2;
    }
    float4 bx;
    bx.x = c0 - 22.5f;
    bx.y = c1 - 22.5f;
    bx.z = c0 + 22.5f;
    bx.w = c1 + 22.5f;
    g_boxes[i] = bx;
    g_scores[i] = (cnt >= 10) ? cnt : -1;
}

// ---------------- fused rank (stable descending) + scatter -------------------
// rank(i) = #{j : s_j > s_i} + #{j : s_j == s_i && j < i}   (== argsort(-s))
// 64 blocks x 256 threads; 4 threads per i, conflict-free j = 4n+q interleave.
__global__ void rank_scatter_kernel() {
    __shared__ int s[NBINS];
    int tid = threadIdx.x;
    for (int l = tid; l < NBINS; l += 256) s[l] = g_scores[l];
    __syncthreads();

    int li = tid >> 2;
    int q = tid & 3;
    int i = blockIdx.x * 64 + li;
    int si = s[i];
    int r = 0;
    #pragma unroll 8
    for (int n = 0; n < 1024; n++) {
        int j = 4 * n + q;
        int sj = s[j];
        r += (sj > si) || (sj == si && j < i);
    }
    r += __shfl_xor_sync(0xFFFFFFFFu, r, 1);
    r += __shfl_xor_sync(0xFFFFFFFFu, r, 2);
    if (q == 0) {
        g_order[r] = i;
        g_bsort[r] = g_boxes[i];
        if (si >= 0)  // is_cluster
            atomicOr(&g_clusterbits[r >> 6], 1ULL << (r & 63));
    }
}

// ---------------- direct greedy NMS + keep output ----------------------------
// Single block, 1024 threads, 4 sorted boxes per thread. Sequential only over
// KEPT boxes (few). Exact reference semantics: iterate candidates in sorted
// order; a kept box suppresses all later boxes with IOU > 0.5.
__global__ void __launch_bounds__(1024) nms_kernel(float* __restrict__ out, int out_size) {
    __shared__ unsigned long long cand[NWORDS];
    __shared__ unsigned long long kept[NWORDS];
    __shared__ int cur_i;
    int tid = threadIdx.x;
    if (tid < NWORDS) { cand[tid] = g_clusterbits[tid]; kept[tid] = 0ULL; }

    float4 bj[4];
    float a2v[4];
    #pragma unroll
    for (int k = 0; k < 4; k++) {
        bj[k] = g_bsort[tid * 4 + k];
        a2v[k] = (bj[k].z - bj[k].x) * (bj[k].w - bj[k].y);
    }

    while (true) {
        __syncthreads();
        if (tid == 0) {
            int found = -1;
            for (int w = 0; w < NWORDS; w++) {
                unsigned long long cw = cand[w];
                if (cw) { found = (w << 6) + __ffsll((long long)cw) - 1; break; }
            }
            cur_i = found;
            if (found >= 0) {
                kept[found >> 6] |= 1ULL << (found & 63);
                cand[found >> 6] &= ~(1ULL << (found & 63));
            }
        }
        __syncthreads();
        int i = cur_i;
        if (i < 0) break;
        float4 bi = g_bsort[i];
        float a1 = (bi.z - bi.x) * (bi.w - bi.y);
        unsigned int sup4 = 0;
        #pragma unroll
        for (int k = 0; k < 4; k++) {
            int j = tid * 4 + k;
            float xx1 = fmaxf(bi.x, bj[k].x);
            float yy1 = fmaxf(bi.y, bj[k].y);
            float xx2 = fminf(bi.z, bj[k].z);
            float yy2 = fminf(bi.w, bj[k].w);
            float inter = fmaxf(xx2 - xx1, 0.0f) * fmaxf(yy2 - yy1, 0.0f);
            float iou = inter / fmaxf(a1 + a2v[k] - inter, 1e-9f);
            if (j > i && iou > 0.5f) sup4 |= 1u << k;
        }
        if (sup4)
            atomicAnd(&cand[tid >> 4],
                      ~((unsigned long long)sup4 << ((tid & 15) * 4)));
    }

    __syncthreads();
    #pragma unroll
    for (int k = 0; k < 4; k++) {
        int r = tid * 4 + k;
        float v = (float)((kept[r >> 6] >> (r & 63)) & 1ULL);
        int pos = 3 * NBINS + g_order[r];
        if (pos < out_size) out[pos] = v;
    }
}

// ============================================================================
extern "C" void kernel_launch(void* const* d_in, const int* in_sizes, int n_in,
                              void* d_out, int out_size) {
    const float* emb = (const float*)d_in[0];   // (1,3,512,512,48) float32
    const float* pm  = (const float*)d_in[1];   // (1,1,512,512,48) float32
    float* out = (float*)d_out;

    erode_z_kernel<<<NVOX / 384, 384>>>(pm);
    erode_yx_kernel<<<dim3(16, 16), 256>>>();
    accum_kernel<<<ACC_BLOCKS, ACC_THREADS>>>(emb);
    finalize_kernel<<<16, 256>>>(out, out_size);
    rank_scatter_kernel<<<64, 256>>>();
    nms_kernel<<<1, 1024>>>(out, out_size);
}

// round 3
// speedup vs baseline: 1.8215x; 1.8215x over previous
#include <cuda_runtime.h>

// ============================================================================
// EstimateCentroids: 9^3 binary erosion (separable, bit-packed) -> hash-binned
// integer segment sums (packed u64 shared atomics, coalesced quad loads) ->
// fused finalize+stable rank sort+scatter -> direct greedy NMS.
// ============================================================================

#define XD 512
#define YD 512
#define ZD 48
#define NROWS (XD * YD)              // 262144
#define NVOX  (NROWS * ZD)           // 12582912
#define NQUADS (NVOX / 4)            // 3145728
#define NBINS 4096
#define NWORDS 64                    // 4096/64

// ---------------- device scratch (static: no allocations allowed) -----------
__device__ unsigned long long g_zbits[NROWS];
__device__ unsigned long long g_xbits[NROWS];
__device__ unsigned long long g_acc1[NBINS];   // (sx+256c)<<32 | (sy+256c)
__device__ unsigned long long g_acc2[NBINS];   // (sz+256c)<<32 | c
__device__ float4 g_bsort[NBINS];
__device__ int    g_order[NBINS];
__device__ unsigned long long g_clusterbits[NWORDS];

// ---------------- erosion along z (binarize, float4 loads) + zero accum -----
// Block = 384 threads, each loads one float4 -> 1536 voxels = 32 rows/block.
__global__ void erode_z_kernel(const float* __restrict__ pm) {
    __shared__ unsigned char nib[384];
    int tid = threadIdx.x;
    int gq = blockIdx.x * 384 + tid;
    // fused zeroing of tiny accumulator arrays
    if (gq < NBINS) { g_acc1[gq] = 0ULL; g_acc2[gq] = 0ULL; }
    if (gq < NWORDS) g_clusterbits[gq] = 0ULL;

    float4 v = ((const float4*)pm)[gq];
    unsigned int n = (v.x > 0.5f ? 1u : 0u) | (v.y > 0.5f ? 2u : 0u) |
                     (v.z > 0.5f ? 4u : 0u) | (v.w > 0.5f ? 8u : 0u);
    nib[tid] = (unsigned char)n;
    __syncthreads();
    if (tid < 32) {
        unsigned long long b = 0ULL;
        #pragma unroll
        for (int k = 0; k < 12; k++)
            b |= (unsigned long long)nib[tid * 12 + k] << (4 * k);
        unsigned long long e = b;
        #pragma unroll
        for (int k = 1; k <= 4; k++)
            e &= (b >> k) & (b << k);
        e &= 0x0000FFFFFFFFFFFFULL;
        g_zbits[blockIdx.x * 32 + tid] = e;
    }
}

// ---------------- fused erosion along y then x (shared tile) -----------------
// Tile: 32x32 output rows, 4-halo each side.
__global__ void erode_yx_kernel() {
    __shared__ unsigned long long sz[40][40];   // [x][y] with halo
    __shared__ unsigned long long sy[40][32];   // y-eroded, x-halo retained
    int tid = threadIdx.x;
    int x0 = blockIdx.x * 32, y0 = blockIdx.y * 32;

    for (int l = tid; l < 40 * 40; l += 256) {
        int xx = l / 40, yy = l - xx * 40;
        int gx = x0 + xx - 4, gy = y0 + yy - 4;
        unsigned long long v = 0ULL;
        if (gx >= 0 && gx < XD && gy >= 0 && gy < YD)
            v = g_zbits[gx * YD + gy];
        sz[xx][yy] = v;
    }
    __syncthreads();

    for (int l = tid; l < 40 * 32; l += 256) {
        int xx = l >> 5, yy = l & 31;
        int gy = y0 + yy;
        unsigned long long r = 0ULL;
        if (gy >= 4 && gy <= YD - 5) {
            r = ~0ULL;
            #pragma unroll
            for (int dy = 0; dy <= 8; dy++)
                r &= sz[xx][yy + dy];
        }
        sy[xx][yy] = r;
    }
    __syncthreads();

    for (int l = tid; l < 32 * 32; l += 256) {
        int xx = l >> 5, yy = l & 31;
        int gx = x0 + xx;
        unsigned long long r = 0ULL;
        if (gx >= 4 && gx <= XD - 5) {
            r = ~0ULL;
            #pragma unroll
            for (int dx = 0; dx <= 8; dx++)
                r &= sy[xx + dx][yy];
        }
        g_xbits[gx * YD + (y0 + yy)] = r;
    }
}

// ---------------- main accumulation -----------------------------------------
// Thread <-> quad of 4 consecutive z-voxels (coalesced float4 loads; quads
// never cross rows since 48 % 4 == 0). One packed u64 shared atomic per valid
// voxel: bits[48:64)=count, [32:48)=x+256, [16:32)=y+256, [0:16)=z+256.
// 148 persistent blocks (1/SM) so the global flush is only 148*8192 lanes.
#define ACC_BLOCKS 148
#define ACC_THREADS 1024
__global__ void __launch_bounds__(ACC_THREADS, 1) accum_kernel(const float* __restrict__ emb) {
    __shared__ unsigned long long sbins[NBINS];
    for (int i = threadIdx.x; i < NBINS; i += ACC_THREADS) sbins[i] = 0ULL;
    __syncthreads();

    const float4* __restrict__ p0 = (const float4*)emb;
    const float4* __restrict__ p1 = (const float4*)(emb + NVOX);
    const float4* __restrict__ p2 = (const float4*)(emb + 2 * NVOX);

    int stride = ACC_BLOCKS * ACC_THREADS;
    for (int q = blockIdx.x * ACC_THREADS + threadIdx.x; q < NQUADS; q += stride) {
        unsigned int row = (unsigned int)q / 12u;
        unsigned int zc = (unsigned int)q - row * 12u;
        unsigned int m4 = (unsigned int)(g_xbits[row] >> (zc * 4)) & 0xFu;
        if (!m4) continue;
        float4 fa = p0[q], fb = p1[q], fc = p2[q];
        float ax[4]  = {fa.x, fa.y, fa.z, fa.w};
        float bx[4]  = {fb.x, fb.y, fb.z, fb.w};
        float cx4[4] = {fc.x, fc.y, fc.z, fc.w};
        #pragma unroll
        for (int k = 0; k < 4; k++) {
            if (!((m4 >> k) & 1u)) continue;
            float a = ax[k], b = bx[k], c2 = cx4[k];
            if (a > -2.0f || b > -2.0f || c2 > -2.0f) {
                int cx = __float2int_rn(a * 25.0f);   // round-half-even == jnp.round
                int cy = __float2int_rn(b * 25.0f);
                int cz = __float2int_rn(c2 * 25.0f);
                unsigned int qx = (unsigned int)min(max(cx + 128, 0), 255);
                unsigned int qy = (unsigned int)min(max(cy + 128, 0), 255);
                unsigned int qz = (unsigned int)min(max(cz + 128, 0), 255);
                unsigned int h = qx * 73856093u ^ qy * 19349663u ^ qz * 83492791u;
                unsigned int seg = h & (NBINS - 1);
                unsigned long long p =
                    (1ULL << 48) |
                    ((unsigned long long)(unsigned int)(cx + 256) << 32) |
                    ((unsigned long long)(unsigned int)(cy + 256) << 16) |
                    (unsigned long long)(unsigned int)(cz + 256);
                atomicAdd(&sbins[seg], p);
            }
        }
    }
    __syncthreads();

    for (int i = threadIdx.x; i < NBINS; i += ACC_THREADS) {
        unsigned long long p = sbins[i];
        if (p) {
            unsigned long long cnt = p >> 48;
            unsigned long long xf = (p >> 32) & 0xFFFFULL;
            unsigned long long yf = (p >> 16) & 0xFFFFULL;
            unsigned long long zf = p & 0xFFFFULL;
            atomicAdd(&g_acc1[i], (xf << 32) | yf);
            atomicAdd(&g_acc2[i], (zf << 32) | cnt);
        }
    }
}

// ---------------- fused finalize + stable rank sort + scatter ----------------
// rank(i) = #{j : s_j > s_i} + #{j : s_j == s_i && j < i}   (== argsort(-s))
// 64 blocks x 256 threads; 4 threads per i, conflict-free j = 4n+q interleave.
// Owner thread (q==0) computes centroid/box, writes output + sorted arrays.
__global__ void rank_scatter_kernel(float* __restrict__ out, int out_size) {
    __shared__ int s[NBINS];
    int tid = threadIdx.x;
    for (int l = tid; l < NBINS; l += 256) {
        int cnt = (int)(g_acc2[l] & 0xFFFFFFFFULL);
        s[l] = (cnt >= 10) ? cnt : -1;
    }
    __syncthreads();

    int li = tid >> 2;
    int q = tid & 3;
    int i = blockIdx.x * 64 + li;
    int si = s[i];
    int r = 0;
    #pragma unroll 8
    for (int n = 0; n < 1024; n++) {
        int j = 4 * n + q;
        int sj = s[j];
        r += (sj > si) || (sj == si && j < i);
    }
    r += __shfl_xor_sync(0xFFFFFFFFu, r, 1);
    r += __shfl_xor_sync(0xFFFFFFFFu, r, 2);
    if (q == 0) {
        unsigned long long a1 = g_acc1[i];
        unsigned long long a2 = g_acc2[i];
        int cnt = (int)(a2 & 0xFFFFFFFFULL);
        int sx = (int)(a1 >> 32) - 256 * cnt;
        int sy = (int)(a1 & 0xFFFFFFFFULL) - 256 * cnt;
        int sz = (int)(a2 >> 32) - 256 * cnt;
        float d = fmaxf((float)cnt, 1.0f);
        float c0 = (float)sx / d;
        float c1 = (float)sy / d;
        float c2 = (float)sz / d;
        if (i * 3 + 2 < out_size) {
            out[i * 3 + 0] = c0;
            out[i * 3 + 1] = c1;
            out[i * 3 + 2] = c2;
        }
        float4 bx;
        bx.x = c0 - 22.5f;
        bx.y = c1 - 22.5f;
        bx.z = c0 + 22.5f;
        bx.w = c1 + 22.5f;
        g_order[r] = i;
        g_bsort[r] = bx;
        if (si >= 0)  // is_cluster
            atomicOr(&g_clusterbits[r >> 6], 1ULL << (r & 63));
    }
}

// ---------------- direct greedy NMS + keep output ----------------------------
// Single block, 1024 threads, 4 sorted boxes per thread. Sequential only over
// KEPT boxes (few). Exact reference semantics: iterate candidates in sorted
// order; a kept box suppresses all later boxes with IOU > 0.5.
__global__ void __launch_bounds__(1024) nms_kernel(float* __restrict__ out, int out_size) {
    __shared__ unsigned long long cand[NWORDS];
    __shared__ unsigned long long kept[NWORDS];
    __shared__ int cur_i;
    int tid = threadIdx.x;
    if (tid < NWORDS) { cand[tid] = g_clusterbits[tid]; kept[tid] = 0ULL; }

    float4 bj[4];
    float a2v[4];
    #pragma unroll
    for (int k = 0; k < 4; k++) {
        bj[k] = g_bsort[tid * 4 + k];
        a2v[k] = (bj[k].z - bj[k].x) * (bj[k].w - bj[k].y);
    }

    while (true) {
        __syncthreads();
        if (tid == 0) {
            int found = -1;
            for (int w = 0; w < NWORDS; w++) {
                unsigned long long cw = cand[w];
                if (cw) { found = (w << 6) + __ffsll((long long)cw) - 1; break; }
            }
            cur_i = found;
            if (found >= 0) {
                kept[found >> 6] |= 1ULL << (found & 63);
                cand[found >> 6] &= ~(1ULL << (found & 63));
            }
        }
        __syncthreads();
        int i = cur_i;
        if (i < 0) break;
        float4 bi = g_bsort[i];
        float a1 = (bi.z - bi.x) * (bi.w - bi.y);
        unsigned int sup4 = 0;
        #pragma unroll
        for (int k = 0; k < 4; k++) {
            int j = tid * 4 + k;
            float xx1 = fmaxf(bi.x, bj[k].x);
            float yy1 = fmaxf(bi.y, bj[k].y);
            float xx2 = fminf(bi.z, bj[k].z);
            float yy2 = fminf(bi.w, bj[k].w);
            float inter = fmaxf(xx2 - xx1, 0.0f) * fmaxf(yy2 - yy1, 0.0f);
            float iou = inter / fmaxf(a1 + a2v[k] - inter, 1e-9f);
            if (j > i && iou > 0.5f) sup4 |= 1u << k;
        }
        if (sup4)
            atomicAnd(&cand[tid >> 4],
                      ~((unsigned long long)sup4 << ((tid & 15) * 4)));
    }

    __syncthreads();
    #pragma unroll
    for (int k = 0; k < 4; k++) {
        int r = tid * 4 + k;
        float v = (float)((kept[r >> 6] >> (r & 63)) & 1ULL);
        int pos = 3 * NBINS + g_order[r];
        if (pos < out_size) out[pos] = v;
    }
}

// ============================================================================
extern "C" void kernel_launch(void* const* d_in, const int* in_sizes, int n_in,
                              void* d_out, int out_size) {
    const float* emb = (const float*)d_in[0];   // (1,3,512,512,48) float32
    const float* pm  = (const float*)d_in[1];   // (1,1,512,512,48) float32
    float* out = (float*)d_out;

    erode_z_kernel<<<NVOX / 1536, 384>>>(pm);
    erode_yx_kernel<<<dim3(16, 16), 256>>>();
    accum_kernel<<<ACC_BLOCKS, ACC_THREADS>>>(emb);
    rank_scatter_kernel<<<64, 256>>>(out, out_size);
    nms_kernel<<<1, 1024>>>(out, out_size);
}

// round 4
// speedup vs baseline: 2.0381x; 1.1189x over previous
#include <cuda_runtime.h>

// ============================================================================
// EstimateCentroids: 9^3 binary erosion (separable, bit-packed) -> hash-binned
// integer segment sums (packed u64 shared atomics, coalesced quad loads) ->
// fused finalize+stable rank sort+scatter (16 threads/key) -> greedy NMS.
// ============================================================================

#define XD 512
#define YD 512
#define ZD 48
#define NROWS (XD * YD)              // 262144
#define NVOX  (NROWS * ZD)           // 12582912
#define NQUADS (NVOX / 4)            // 3145728
#define NBINS 4096
#define NWORDS 64                    // 4096/64

// ---------------- device scratch (static: no allocations allowed) -----------
__device__ unsigned long long g_zbits[NROWS];
__device__ unsigned long long g_xbits[NROWS];
__device__ unsigned long long g_acc1[NBINS];   // (sx+256c)<<32 | (sy+256c)
__device__ unsigned long long g_acc2[NBINS];   // (sz+256c)<<32 | c
__device__ float4 g_bsort[NBINS];
__device__ int    g_order[NBINS];
__device__ unsigned long long g_clusterbits[NWORDS];

// ---------------- erosion along z (binarize, float4 loads) + zero accum -----
// Block = 384 threads, each loads one float4 -> 1536 voxels = 32 rows/block.
__global__ void erode_z_kernel(const float* __restrict__ pm) {
    __shared__ unsigned char nib[384];
    int tid = threadIdx.x;
    int gq = blockIdx.x * 384 + tid;
    // fused zeroing of tiny accumulator arrays
    if (gq < NBINS) { g_acc1[gq] = 0ULL; g_acc2[gq] = 0ULL; }
    if (gq < NWORDS) g_clusterbits[gq] = 0ULL;

    float4 v = ((const float4*)pm)[gq];
    unsigned int n = (v.x > 0.5f ? 1u : 0u) | (v.y > 0.5f ? 2u : 0u) |
                     (v.z > 0.5f ? 4u : 0u) | (v.w > 0.5f ? 8u : 0u);
    nib[tid] = (unsigned char)n;
    __syncthreads();
    if (tid < 32) {
        unsigned long long b = 0ULL;
        #pragma unroll
        for (int k = 0; k < 12; k++)
            b |= (unsigned long long)nib[tid * 12 + k] << (4 * k);
        unsigned long long e = b;
        #pragma unroll
        for (int k = 1; k <= 4; k++)
            e &= (b >> k) & (b << k);
        e &= 0x0000FFFFFFFFFFFFULL;
        g_zbits[blockIdx.x * 32 + tid] = e;
    }
}

// ---------------- fused erosion along y then x (shared tile) -----------------
// Tile: 32x32 output rows, 4-halo each side.
__global__ void erode_yx_kernel() {
    __shared__ unsigned long long sz[40][40];   // [x][y] with halo
    __shared__ unsigned long long sy[40][32];   // y-eroded, x-halo retained
    int tid = threadIdx.x;
    int x0 = blockIdx.x * 32, y0 = blockIdx.y * 32;

    for (int l = tid; l < 40 * 40; l += 256) {
        int xx = l / 40, yy = l - xx * 40;
        int gx = x0 + xx - 4, gy = y0 + yy - 4;
        unsigned long long v = 0ULL;
        if (gx >= 0 && gx < XD && gy >= 0 && gy < YD)
            v = g_zbits[gx * YD + gy];
        sz[xx][yy] = v;
    }
    __syncthreads();

    for (int l = tid; l < 40 * 32; l += 256) {
        int xx = l >> 5, yy = l & 31;
        int gy = y0 + yy;
        unsigned long long r = 0ULL;
        if (gy >= 4 && gy <= YD - 5) {
            r = ~0ULL;
            #pragma unroll
            for (int dy = 0; dy <= 8; dy++)
                r &= sz[xx][yy + dy];
        }
        sy[xx][yy] = r;
    }
    __syncthreads();

    for (int l = tid; l < 32 * 32; l += 256) {
        int xx = l >> 5, yy = l & 31;
        int gx = x0 + xx;
        unsigned long long r = 0ULL;
        if (gx >= 4 && gx <= XD - 5) {
            r = ~0ULL;
            #pragma unroll
            for (int dx = 0; dx <= 8; dx++)
                r &= sy[xx + dx][yy];
        }
        g_xbits[gx * YD + (y0 + yy)] = r;
    }
}

// ---------------- main accumulation -----------------------------------------
// Thread <-> quad of 4 consecutive z-voxels (coalesced float4 loads; quads
// never cross rows since 48 % 4 == 0). One packed u64 shared atomic per valid
// voxel: bits[48:64)=count, [32:48)=x+256, [16:32)=y+256, [0:16)=z+256.
// 148 persistent blocks (1/SM) so the global flush is only 148*8192 lanes.
#define ACC_BLOCKS 148
#define ACC_THREADS 1024
__global__ void __launch_bounds__(ACC_THREADS, 1) accum_kernel(const float* __restrict__ emb) {
    __shared__ unsigned long long sbins[NBINS];
    for (int i = threadIdx.x; i < NBINS; i += ACC_THREADS) sbins[i] = 0ULL;
    __syncthreads();

    const float4* __restrict__ p0 = (const float4*)emb;
    const float4* __restrict__ p1 = (const float4*)(emb + NVOX);
    const float4* __restrict__ p2 = (const float4*)(emb + 2 * NVOX);

    int stride = ACC_BLOCKS * ACC_THREADS;
    for (int q = blockIdx.x * ACC_THREADS + threadIdx.x; q < NQUADS; q += stride) {
        unsigned int row = (unsigned int)q / 12u;
        unsigned int zc = (unsigned int)q - row * 12u;
        unsigned int m4 = (unsigned int)(g_xbits[row] >> (zc * 4)) & 0xFu;
        if (!m4) continue;
        float4 fa = p0[q], fb = p1[q], fc = p2[q];
        float ax[4]  = {fa.x, fa.y, fa.z, fa.w};
        float bx[4]  = {fb.x, fb.y, fb.z, fb.w};
        float cx4[4] = {fc.x, fc.y, fc.z, fc.w};
        #pragma unroll
        for (int k = 0; k < 4; k++) {
            if (!((m4 >> k) & 1u)) continue;
            float a = ax[k], b = bx[k], c2 = cx4[k];
            if (a > -2.0f || b > -2.0f || c2 > -2.0f) {
                int cx = __float2int_rn(a * 25.0f);   // round-half-even == jnp.round
                int cy = __float2int_rn(b * 25.0f);
                int cz = __float2int_rn(c2 * 25.0f);
                unsigned int qx = (unsigned int)min(max(cx + 128, 0), 255);
                unsigned int qy = (unsigned int)min(max(cy + 128, 0), 255);
                unsigned int qz = (unsigned int)min(max(cz + 128, 0), 255);
                unsigned int h = qx * 73856093u ^ qy * 19349663u ^ qz * 83492791u;
                unsigned int seg = h & (NBINS - 1);
                unsigned long long p =
                    (1ULL << 48) |
                    ((unsigned long long)(unsigned int)(cx + 256) << 32) |
                    ((unsigned long long)(unsigned int)(cy + 256) << 16) |
                    (unsigned long long)(unsigned int)(cz + 256);
                atomicAdd(&sbins[seg], p);
            }
        }
    }
    __syncthreads();

    for (int i = threadIdx.x; i < NBINS; i += ACC_THREADS) {
        unsigned long long p = sbins[i];
        if (p) {
            unsigned long long cnt = p >> 48;
            unsigned long long xf = (p >> 32) & 0xFFFFULL;
            unsigned long long yf = (p >> 16) & 0xFFFFULL;
            unsigned long long zf = p & 0xFFFFULL;
            atomicAdd(&g_acc1[i], (xf << 32) | yf);
            atomicAdd(&g_acc2[i], (zf << 32) | cnt);
        }
    }
}

// ---------------- fused finalize + stable rank sort + scatter ----------------
// rank(i) = #{j : s_j > s_i} + #{j : s_j == s_i && j < i}   (== argsort(-s))
// 128 blocks x 512 threads; 16 threads per i, conflict-free j = 16n+q
// interleave (16 distinct banks, 2-way broadcast). Shfl-tree reduce over the
// 16-lane group; owner thread computes centroid/box and writes outputs.
__global__ void __launch_bounds__(512) rank_scatter_kernel(float* __restrict__ out, int out_size) {
    __shared__ int s[NBINS];
    int tid = threadIdx.x;
    for (int l = tid; l < NBINS; l += 512) {
        int cnt = (int)(g_acc2[l] & 0xFFFFFFFFULL);
        s[l] = (cnt >= 10) ? cnt : -1;
    }
    __syncthreads();

    int li = tid >> 4;                 // 0..31 : which key in this block
    int q  = tid & 15;                 // lane within key group
    int i  = blockIdx.x * 32 + li;
    int si = s[i];
    int r = 0;
    #pragma unroll 8
    for (int n = 0; n < 256; n++) {
        int j = 16 * n + q;
        int sj = s[j];
        r += (sj > si) || (sj == si && j < i);
    }
    r += __shfl_xor_sync(0xFFFFFFFFu, r, 1);
    r += __shfl_xor_sync(0xFFFFFFFFu, r, 2);
    r += __shfl_xor_sync(0xFFFFFFFFu, r, 4);
    r += __shfl_xor_sync(0xFFFFFFFFu, r, 8);
    if (q == 0) {
        unsigned long long a1 = g_acc1[i];
        unsigned long long a2 = g_acc2[i];
        int cnt = (int)(a2 & 0xFFFFFFFFULL);
        int sx = (int)(a1 >> 32) - 256 * cnt;
        int sy = (int)(a1 & 0xFFFFFFFFULL) - 256 * cnt;
        int sz = (int)(a2 >> 32) - 256 * cnt;
        float d = fmaxf((float)cnt, 1.0f);
        float c0 = (float)sx / d;
        float c1 = (float)sy / d;
        float c2 = (float)sz / d;
        if (i * 3 + 2 < out_size) {
            out[i * 3 + 0] = c0;
            out[i * 3 + 1] = c1;
            out[i * 3 + 2] = c2;
        }
        float4 bx;
        bx.x = c0 - 22.5f;
        bx.y = c1 - 22.5f;
        bx.z = c0 + 22.5f;
        bx.w = c1 + 22.5f;
        g_order[r] = i;
        g_bsort[r] = bx;
        if (si >= 0)  // is_cluster
            atomicOr(&g_clusterbits[r >> 6], 1ULL << (r & 63));
    }
}

// ---------------- direct greedy NMS + keep output ----------------------------
// Single block, 1024 threads, 4 sorted boxes per thread. Sequential only over
// KEPT boxes (few). Exact reference semantics: iterate candidates in sorted
// order; a kept box suppresses all later boxes with IOU > 0.5.
__global__ void __launch_bounds__(1024) nms_kernel(float* __restrict__ out, int out_size) {
    __shared__ unsigned long long cand[NWORDS];
    __shared__ unsigned long long kept[NWORDS];
    __shared__ int cur_i;
    int tid = threadIdx.x;
    if (tid < NWORDS) { cand[tid] = g_clusterbits[tid]; kept[tid] = 0ULL; }

    float4 bj[4];
    float a2v[4];
    #pragma unroll
    for (int k = 0; k < 4; k++) {
        bj[k] = g_bsort[tid * 4 + k];
        a2v[k] = (bj[k].z - bj[k].x) * (bj[k].w - bj[k].y);
    }

    while (true) {
        __syncthreads();
        if (tid == 0) {
            int found = -1;
            for (int w = 0; w < NWORDS; w++) {
                unsigned long long cw = cand[w];
                if (cw) { found = (w << 6) + __ffsll((long long)cw) - 1; break; }
            }
            cur_i = found;
            if (found >= 0) {
                kept[found >> 6] |= 1ULL << (found & 63);
                cand[found >> 6] &= ~(1ULL << (found & 63));
            }
        }
        __syncthreads();
        int i = cur_i;
        if (i < 0) break;
        float4 bi = g_bsort[i];
        float a1 = (bi.z - bi.x) * (bi.w - bi.y);
        unsigned int sup4 = 0;
        #pragma unroll
        for (int k = 0; k < 4; k++) {
            int j = tid * 4 + k;
            float xx1 = fmaxf(bi.x, bj[k].x);
            float yy1 = fmaxf(bi.y, bj[k].y);
            float xx2 = fminf(bi.z, bj[k].z);
            float yy2 = fminf(bi.w, bj[k].w);
            float inter = fmaxf(xx2 - xx1, 0.0f) * fmaxf(yy2 - yy1, 0.0f);
            float iou = inter / fmaxf(a1 + a2v[k] - inter, 1e-9f);
            if (j > i && iou > 0.5f) sup4 |= 1u << k;
        }
        if (sup4)
            atomicAnd(&cand[tid >> 4],
                      ~((unsigned long long)sup4 << ((tid & 15) * 4)));
    }

    __syncthreads();
    #pragma unroll
    for (int k = 0; k < 4; k++) {
        int r = tid * 4 + k;
        float v = (float)((kept[r >> 6] >> (r & 63)) & 1ULL);
        int pos = 3 * NBINS + g_order[r];
        if (pos < out_size) out[pos] = v;
    }
}

// ============================================================================
extern "C" void kernel_launch(void* const* d_in, const int* in_sizes, int n_in,
                              void* d_out, int out_size) {
    const float* emb = (const float*)d_in[0];   // (1,3,512,512,48) float32
    const float* pm  = (const float*)d_in[1];   // (1,1,512,512,48) float32
    float* out = (float*)d_out;

    erode_z_kernel<<<NVOX / 1536, 384>>>(pm);
    erode_yx_kernel<<<dim3(16, 16), 256>>>();
    accum_kernel<<<ACC_BLOCKS, ACC_THREADS>>>(emb);
    rank_scatter_kernel<<<128, 512>>>(out, out_size);
    nms_kernel<<<1, 1024>>>(out, out_size);
}

// round 5
// speedup vs baseline: 2.0484x; 1.0051x over previous
#include <cuda_runtime.h>

// ============================================================================
// EstimateCentroids, 2 kernels:
//  K1 (persistent, grid = #SMs, software grid barriers):
//     phase A: binarize + z-erosion (bit-packed)     -> g_zbits
//     phase B: y- then x-erosion (shared tiles)      -> g_xbits
//     phase C: hash-binned packed-u64 shared-atomic segment sums -> g_acc*
//  K2: stable rank sort + scatter (32 lanes/key), last block runs greedy NMS.
// ============================================================================

#define XD 512
#define YD 512
#define ZD 48
#define NROWS (XD * YD)              // 262144
#define NVOX  (NROWS * ZD)           // 12582912
#define NQUADS (NVOX / 4)            // 3145728
#define NCHUNKS (NQUADS / 3072)      // 1024
#define NBINS 4096
#define NWORDS 64

typedef unsigned long long u64;

// ---------------- device scratch (static: no allocations allowed) -----------
__device__ u64 g_zbits[NROWS];
__device__ u64 g_xbits[NROWS];
__device__ u64 g_acc1[NBINS];        // (sx+256c)<<32 | (sy+256c)
__device__ u64 g_acc2[NBINS];        // (sz+256c)<<32 | c
__device__ float4 g_bsort[NBINS];
__device__ int    g_order[NBINS];
__device__ u64 g_clusterbits[NWORDS];
__device__ unsigned int g_bar[4];    // grid-barrier counters (reset by K2)
__device__ unsigned int g_done;      // K2 completion counter (reset by its last block)

// ---------------- software grid barrier (all blocks resident) ---------------
__device__ __forceinline__ void grid_bar(int phase) {
    __threadfence();                  // each thread flushes its own writes
    __syncthreads();
    if (threadIdx.x == 0) {
        atomicAdd(&g_bar[phase], 1u);
        while (*(volatile unsigned int*)&g_bar[phase] < gridDim.x) { }
    }
    __syncthreads();
}

// ============================================================================
// K1: erode_z -> erode_yx -> accumulate   (one persistent kernel)
// ============================================================================
__global__ void __launch_bounds__(1024, 1) mega_kernel(const float* __restrict__ emb,
                                                       const float* __restrict__ pm) {
    __shared__ __align__(16) unsigned char smem_raw[32768];
    int tid = threadIdx.x;

    // -------- phase A: binarize + z-erosion, 3072 quads (256 rows) per chunk
    {
        unsigned char* nib = smem_raw;
        const float4* pm4 = (const float4*)pm;
        for (int c = blockIdx.x; c < NCHUNKS; c += gridDim.x) {
            __syncthreads();          // protect nib reuse across chunks
            #pragma unroll
            for (int r = 0; r < 3; r++) {
                float4 v = pm4[c * 3072 + r * 1024 + tid];
                unsigned int n = (v.x > 0.5f ? 1u : 0u) | (v.y > 0.5f ? 2u : 0u) |
                                 (v.z > 0.5f ? 4u : 0u) | (v.w > 0.5f ? 8u : 0u);
                nib[r * 1024 + tid] = (unsigned char)n;
            }
            __syncthreads();
            if (tid < 256) {
                u64 b = 0ULL;
                #pragma unroll
                for (int k = 0; k < 12; k++)
                    b |= (u64)nib[tid * 12 + k] << (4 * k);
                u64 e = b;
                #pragma unroll
                for (int k = 1; k <= 4; k++)
                    e &= (b >> k) & (b << k);
                e &= 0x0000FFFFFFFFFFFFULL;
                g_zbits[c * 256 + tid] = e;
            }
        }
        // fused zeroing of accumulator arrays (done before barrier 0)
        if (blockIdx.x == 0) {
            for (int l = tid; l < NBINS; l += 1024) { g_acc1[l] = 0ULL; g_acc2[l] = 0ULL; }
            if (tid < NWORDS) g_clusterbits[tid] = 0ULL;
        }
    }
    grid_bar(0);

    // -------- phase B: y then x erosion, 32x32-row tiles with 4-halo --------
    {
        u64* szt = (u64*)smem_raw;                     // [40*40]
        u64* syt = (u64*)(smem_raw + 12800);           // [40*32]
        for (int t = blockIdx.x; t < 256; t += gridDim.x) {
            __syncthreads();
            int x0 = (t >> 4) * 32, y0 = (t & 15) * 32;
            for (int l = tid; l < 1600; l += 1024) {
                int xx = l / 40, yy = l - xx * 40;
                int gx = x0 + xx - 4, gy = y0 + yy - 4;
                u64 v = 0ULL;
                if (gx >= 0 && gx < XD && gy >= 0 && gy < YD)
                    v = g_zbits[gx * YD + gy];
                szt[xx * 40 + yy] = v;
            }
            __syncthreads();
            for (int l = tid; l < 1280; l += 1024) {
                int xx = l >> 5, yy = l & 31;
                int gy = y0 + yy;
                u64 r = 0ULL;
                if (gy >= 4 && gy <= YD - 5) {
                    r = ~0ULL;
                    #pragma unroll
                    for (int dy = 0; dy <= 8; dy++)
                        r &= szt[xx * 40 + yy + dy];
                }
                syt[xx * 32 + yy] = r;
            }
            __syncthreads();
            {
                int xx = tid >> 5, yy = tid & 31;
                int gx = x0 + xx;
                u64 r = 0ULL;
                if (gx >= 4 && gx <= XD - 5) {
                    r = ~0ULL;
                    #pragma unroll
                    for (int dx = 0; dx <= 8; dx++)
                        r &= syt[(xx + dx) * 32 + yy];
                }
                g_xbits[gx * YD + (y0 + yy)] = r;
            }
        }
    }
    grid_bar(1);

    // -------- phase C: hash-binned packed accumulation ----------------------
    {
        u64* sbins = (u64*)smem_raw;
        for (int i = tid; i < NBINS; i += 1024) sbins[i] = 0ULL;
        __syncthreads();

        const float4* __restrict__ p0 = (const float4*)emb;
        const float4* __restrict__ p1 = (const float4*)(emb + NVOX);
        const float4* __restrict__ p2 = (const float4*)(emb + 2 * NVOX);

        int stride = gridDim.x * 1024;
        for (int q = blockIdx.x * 1024 + tid; q < NQUADS; q += stride) {
            unsigned int row = (unsigned int)q / 12u;
            unsigned int zc = (unsigned int)q - row * 12u;
            unsigned int m4 = (unsigned int)(g_xbits[row] >> (zc * 4)) & 0xFu;
            if (!m4) continue;
            float4 fa = p0[q], fb = p1[q], fc = p2[q];
            float ax[4]  = {fa.x, fa.y, fa.z, fa.w};
            float bx[4]  = {fb.x, fb.y, fb.z, fb.w};
            float cx4[4] = {fc.x, fc.y, fc.z, fc.w};
            #pragma unroll
            for (int k = 0; k < 4; k++) {
                if (!((m4 >> k) & 1u)) continue;
                float a = ax[k], b = bx[k], c2 = cx4[k];
                if (a > -2.0f || b > -2.0f || c2 > -2.0f) {
                    int cx = __float2int_rn(a * 25.0f);   // round-half-even
                    int cy = __float2int_rn(b * 25.0f);
                    int cz = __float2int_rn(c2 * 25.0f);
                    unsigned int qx = (unsigned int)min(max(cx + 128, 0), 255);
                    unsigned int qy = (unsigned int)min(max(cy + 128, 0), 255);
                    unsigned int qz = (unsigned int)min(max(cz + 128, 0), 255);
                    unsigned int h = qx * 73856093u ^ qy * 19349663u ^ qz * 83492791u;
                    unsigned int seg = h & (NBINS - 1);
                    u64 p = (1ULL << 48) |
                            ((u64)(unsigned int)(cx + 256) << 32) |
                            ((u64)(unsigned int)(cy + 256) << 16) |
                            (u64)(unsigned int)(cz + 256);
                    atomicAdd(&sbins[seg], p);
                }
            }
        }
        __syncthreads();

        for (int i = tid; i < NBINS; i += 1024) {
            u64 p = sbins[i];
            if (p) {
                u64 cnt = p >> 48;
                u64 xf = (p >> 32) & 0xFFFFULL;
                u64 yf = (p >> 16) & 0xFFFFULL;
                u64 zf = p & 0xFFFFULL;
                atomicAdd(&g_acc1[i], (xf << 32) | yf);
                atomicAdd(&g_acc2[i], (zf << 32) | cnt);
            }
        }
    }
}

// ============================================================================
// K2: finalize + stable rank sort + scatter; last block runs greedy NMS.
// rank(i) = #{j : s_j > s_i} + #{j : s_j == s_i && j < i}   (== argsort(-s))
// 256 blocks x 512 threads; full warp (32 lanes) per key, 128 iters each.
// ============================================================================
__global__ void __launch_bounds__(512) rank_nms_kernel(float* __restrict__ out, int out_size) {
    __shared__ int s[NBINS];
    __shared__ u64 cand[NWORDS];
    __shared__ u64 kept[NWORDS];
    __shared__ int cur_i;
    __shared__ unsigned int is_last;
    int tid = threadIdx.x;

    // reset K1's grid-barrier counters for the next replay
    if (blockIdx.x == 0 && tid < 4) g_bar[tid] = 0;

    for (int l = tid; l < NBINS; l += 512) {
        int cnt = (int)(g_acc2[l] & 0xFFFFFFFFULL);
        s[l] = (cnt >= 10) ? cnt : -1;
    }
    __syncthreads();

    int w = tid >> 5;                  // warp = key within block
    int lane = tid & 31;
    int i = blockIdx.x * 16 + w;
    int si = s[i];
    int r = 0;
    #pragma unroll 8
    for (int n = 0; n < 128; n++) {
        int j = n * 32 + lane;
        int sj = s[j];
        r += (sj > si) || (sj == si && j < i);
    }
    #pragma unroll
    for (int d = 1; d < 32; d <<= 1)
        r += __shfl_xor_sync(0xFFFFFFFFu, r, d);

    if (lane == 0) {
        u64 a1 = g_acc1[i];
        u64 a2 = g_acc2[i];
        int cnt = (int)(a2 & 0xFFFFFFFFULL);
        int sx = (int)(a1 >> 32) - 256 * cnt;
        int sy = (int)(a1 & 0xFFFFFFFFULL) - 256 * cnt;
        int sz = (int)(a2 >> 32) - 256 * cnt;
        float d = fmaxf((float)cnt, 1.0f);
        float c0 = (float)sx / d;
        float c1 = (float)sy / d;
        float c2 = (float)sz / d;
        if (i * 3 + 2 < out_size) {
            out[i * 3 + 0] = c0;
            out[i * 3 + 1] = c1;
            out[i * 3 + 2] = c2;
        }
        float4 bx;
        bx.x = c0 - 22.5f;
        bx.y = c1 - 22.5f;
        bx.z = c0 + 22.5f;
        bx.w = c1 + 22.5f;
        g_order[r] = i;
        g_bsort[r] = bx;
        if (si >= 0)  // is_cluster
            atomicOr(&g_clusterbits[r >> 6], 1ULL << (r & 63));
    }

    // ---- completion detection: last block runs NMS --------------------------
    __threadfence();
    __syncthreads();
    if (tid == 0)
        is_last = (atomicAdd(&g_done, 1u) == gridDim.x - 1) ? 1u : 0u;
    __syncthreads();
    if (!is_last) return;
    if (tid == 0) g_done = 0;          // reset for next replay

    // ---- greedy NMS: 512 threads, 8 sorted boxes per thread -----------------
    if (tid < NWORDS) { cand[tid] = g_clusterbits[tid]; kept[tid] = 0ULL; }

    float4 bj[8];
    float a2v[8];
    #pragma unroll
    for (int k = 0; k < 8; k++) {
        bj[k] = g_bsort[tid * 8 + k];
        a2v[k] = (bj[k].z - bj[k].x) * (bj[k].w - bj[k].y);
    }

    while (true) {
        __syncthreads();
        if (tid == 0) {
            int found = -1;
            for (int ww = 0; ww < NWORDS; ww++) {
                u64 cw = cand[ww];
                if (cw) { found = (ww << 6) + __ffsll((long long)cw) - 1; break; }
            }
            cur_i = found;
            if (found >= 0) {
                kept[found >> 6] |= 1ULL << (found & 63);
                cand[found >> 6] &= ~(1ULL << (found & 63));
            }
        }
        __syncthreads();
        int ii = cur_i;
        if (ii < 0) break;
        float4 bi = g_bsort[ii];
        float a1 = (bi.z - bi.x) * (bi.w - bi.y);
        unsigned int sup8 = 0;
        #pragma unroll
        for (int k = 0; k < 8; k++) {
            int j = tid * 8 + k;
            float xx1 = fmaxf(bi.x, bj[k].x);
            float yy1 = fmaxf(bi.y, bj[k].y);
            float xx2 = fminf(bi.z, bj[k].z);
            float yy2 = fminf(bi.w, bj[k].w);
            float inter = fmaxf(xx2 - xx1, 0.0f) * fmaxf(yy2 - yy1, 0.0f);
            float iou = inter / fmaxf(a1 + a2v[k] - inter, 1e-9f);
            if (j > ii && iou > 0.5f) sup8 |= 1u << k;
        }
        if (sup8)
            atomicAnd(&cand[tid >> 3],
                      ~((u64)sup8 << ((tid & 7) * 8)));
    }

    __syncthreads();
    #pragma unroll
    for (int k = 0; k < 8; k++) {
        int rr = tid * 8 + k;
        float v = (float)((kept[rr >> 6] >> (rr & 63)) & 1ULL);
        int pos = 3 * NBINS + g_order[rr];
        if (pos < out_size) out[pos] = v;
    }
}

// ============================================================================
extern "C" void kernel_launch(void* const* d_in, const int* in_sizes, int n_in,
                              void* d_out, int out_size) {
    const float* emb = (const float*)d_in[0];   // (1,3,512,512,48) float32
    const float* pm  = (const float*)d_in[1];   // (1,1,512,512,48) float32
    float* out = (float*)d_out;

    static int sms = 0;
    if (sms == 0) cudaDeviceGetAttribute(&sms, cudaDevAttrMultiProcessorCount, 0);

    mega_kernel<<<sms, 1024>>>(emb, pm);
    rank_nms_kernel<<<256, 512>>>(out, out_size);
}

// round 6
// speedup vs baseline: 2.1102x; 1.0302x over previous
#include <cuda_runtime.h>

// ============================================================================
// EstimateCentroids, 2 kernels:
//  K1 (persistent, grid = #SMs, software grid barriers):
//     phase A: binarize + z-erosion (bit-packed)     -> g_zbits
//     phase B: y- then x-erosion (shared tiles)      -> g_xbits
//     phase C: hash-binned packed-u64 shared-atomic segment sums -> g_acc*
//  K2: packed-key stable rank sort (int4 LDS, warp/key, single wave) +
//      scatter; last block runs greedy NMS inline.
// ============================================================================

#define XD 512
#define YD 512
#define ZD 48
#define NROWS (XD * YD)              // 262144
#define NVOX  (NROWS * ZD)           // 12582912
#define NQUADS (NVOX / 4)            // 3145728
#define NCHUNKS (NQUADS / 3072)      // 1024
#define NBINS 4096
#define NWORDS 64

typedef unsigned long long u64;

// ---------------- device scratch (static: no allocations allowed) -----------
__device__ u64 g_zbits[NROWS];
__device__ u64 g_xbits[NROWS];
__device__ u64 g_acc1[NBINS];        // (sx+256c)<<32 | (sy+256c)
__device__ u64 g_acc2[NBINS];        // (sz+256c)<<32 | c
__device__ float4 g_bsort[NBINS];
__device__ int    g_order[NBINS];
__device__ u64 g_clusterbits[NWORDS];
__device__ unsigned int g_bar[4];    // grid-barrier counters (reset by K2)
__device__ unsigned int g_done;      // K2 completion counter (reset by its last block)

// ---------------- software grid barrier (all blocks resident) ---------------
__device__ __forceinline__ void grid_bar(int phase) {
    __threadfence();                  // each thread flushes its own writes
    __syncthreads();
    if (threadIdx.x == 0) {
        atomicAdd(&g_bar[phase], 1u);
        while (*(volatile unsigned int*)&g_bar[phase] < gridDim.x) { }
    }
    __syncthreads();
}

// ============================================================================
// K1: erode_z -> erode_yx -> accumulate   (one persistent kernel)
// ============================================================================
__global__ void __launch_bounds__(1024, 1) mega_kernel(const float* __restrict__ emb,
                                                       const float* __restrict__ pm) {
    __shared__ __align__(16) unsigned char smem_raw[32768];
    int tid = threadIdx.x;

    // -------- phase A: binarize + z-erosion, 3072 quads (256 rows) per chunk
    {
        unsigned char* nib = smem_raw;
        const float4* pm4 = (const float4*)pm;
        for (int c = blockIdx.x; c < NCHUNKS; c += gridDim.x) {
            __syncthreads();          // protect nib reuse across chunks
            #pragma unroll
            for (int r = 0; r < 3; r++) {
                float4 v = pm4[c * 3072 + r * 1024 + tid];
                unsigned int n = (v.x > 0.5f ? 1u : 0u) | (v.y > 0.5f ? 2u : 0u) |
                                 (v.z > 0.5f ? 4u : 0u) | (v.w > 0.5f ? 8u : 0u);
                nib[r * 1024 + tid] = (unsigned char)n;
            }
            __syncthreads();
            if (tid < 256) {
                u64 b = 0ULL;
                #pragma unroll
                for (int k = 0; k < 12; k++)
                    b |= (u64)nib[tid * 12 + k] << (4 * k);
                u64 e = b;
                #pragma unroll
                for (int k = 1; k <= 4; k++)
                    e &= (b >> k) & (b << k);
                e &= 0x0000FFFFFFFFFFFFULL;
                g_zbits[c * 256 + tid] = e;
            }
        }
        // fused zeroing of accumulator arrays (done before barrier 0)
        if (blockIdx.x == 0) {
            for (int l = tid; l < NBINS; l += 1024) { g_acc1[l] = 0ULL; g_acc2[l] = 0ULL; }
            if (tid < NWORDS) g_clusterbits[tid] = 0ULL;
        }
    }
    grid_bar(0);

    // -------- phase B: y then x erosion, 32x32-row tiles with 4-halo --------
    {
        u64* szt = (u64*)smem_raw;                     // [40*40]
        u64* syt = (u64*)(smem_raw + 12800);           // [40*32]
        for (int t = blockIdx.x; t < 256; t += gridDim.x) {
            __syncthreads();
            int x0 = (t >> 4) * 32, y0 = (t & 15) * 32;
            for (int l = tid; l < 1600; l += 1024) {
                int xx = l / 40, yy = l - xx * 40;
                int gx = x0 + xx - 4, gy = y0 + yy - 4;
                u64 v = 0ULL;
                if (gx >= 0 && gx < XD && gy >= 0 && gy < YD)
                    v = g_zbits[gx * YD + gy];
                szt[xx * 40 + yy] = v;
            }
            __syncthreads();
            for (int l = tid; l < 1280; l += 1024) {
                int xx = l >> 5, yy = l & 31;
                int gy = y0 + yy;
                u64 r = 0ULL;
                if (gy >= 4 && gy <= YD - 5) {
                    r = ~0ULL;
                    #pragma unroll
                    for (int dy = 0; dy <= 8; dy++)
                        r &= szt[xx * 40 + yy + dy];
                }
                syt[xx * 32 + yy] = r;
            }
            __syncthreads();
            {
                int xx = tid >> 5, yy = tid & 31;
                int gx = x0 + xx;
                u64 r = 0ULL;
                if (gx >= 4 && gx <= XD - 5) {
                    r = ~0ULL;
                    #pragma unroll
                    for (int dx = 0; dx <= 8; dx++)
                        r &= syt[(xx + dx) * 32 + yy];
                }
                g_xbits[gx * YD + (y0 + yy)] = r;
            }
        }
    }
    grid_bar(1);

    // -------- phase C: hash-binned packed accumulation ----------------------
    {
        u64* sbins = (u64*)smem_raw;
        for (int i = tid; i < NBINS; i += 1024) sbins[i] = 0ULL;
        __syncthreads();

        const float4* __restrict__ p0 = (const float4*)emb;
        const float4* __restrict__ p1 = (const float4*)(emb + NVOX);
        const float4* __restrict__ p2 = (const float4*)(emb + 2 * NVOX);

        int stride = gridDim.x * 1024;
        for (int q = blockIdx.x * 1024 + tid; q < NQUADS; q += stride) {
            unsigned int row = (unsigned int)q / 12u;
            unsigned int zc = (unsigned int)q - row * 12u;
            unsigned int m4 = (unsigned int)(g_xbits[row] >> (zc * 4)) & 0xFu;
            if (!m4) continue;
            float4 fa = p0[q], fb = p1[q], fc = p2[q];
            float ax[4]  = {fa.x, fa.y, fa.z, fa.w};
            float bx[4]  = {fb.x, fb.y, fb.z, fb.w};
            float cx4[4] = {fc.x, fc.y, fc.z, fc.w};
            #pragma unroll
            for (int k = 0; k < 4; k++) {
                if (!((m4 >> k) & 1u)) continue;
                float a = ax[k], b = bx[k], c2 = cx4[k];
                if (a > -2.0f || b > -2.0f || c2 > -2.0f) {
                    int cx = __float2int_rn(a * 25.0f);   // round-half-even
                    int cy = __float2int_rn(b * 25.0f);
                    int cz = __float2int_rn(c2 * 25.0f);
                    unsigned int qx = (unsigned int)min(max(cx + 128, 0), 255);
                    unsigned int qy = (unsigned int)min(max(cy + 128, 0), 255);
                    unsigned int qz = (unsigned int)min(max(cz + 128, 0), 255);
                    unsigned int h = qx * 73856093u ^ qy * 19349663u ^ qz * 83492791u;
                    unsigned int seg = h & (NBINS - 1);
                    u64 p = (1ULL << 48) |
                            ((u64)(unsigned int)(cx + 256) << 32) |
                            ((u64)(unsigned int)(cy + 256) << 16) |
                            (u64)(unsigned int)(cz + 256);
                    atomicAdd(&sbins[seg], p);
                }
            }
        }
        __syncthreads();

        for (int i = tid; i < NBINS; i += 1024) {
            u64 p = sbins[i];
            if (p) {
                u64 cnt = p >> 48;
                u64 xf = (p >> 32) & 0xFFFFULL;
                u64 yf = (p >> 16) & 0xFFFFULL;
                u64 zf = p & 0xFFFFULL;
                atomicAdd(&g_acc1[i], (xf << 32) | yf);
                atomicAdd(&g_acc2[i], (zf << 32) | cnt);
            }
        }
    }
}

// ============================================================================
// K2: packed-key stable rank sort + scatter + NMS (last block).
// Key k_j = ((s_j+1)<<12) | (4095-j): k_j > k_i  <=>  (s_j > s_i) or
// (s_j == s_i && j < i), so rank(i) = #{j : k_j > k_i} == argsort(-s) rank.
// 128 blocks x 1024 threads, single wave; warp per key, int4 LDS compares.
// ============================================================================
__global__ void __launch_bounds__(1024) rank_nms_kernel(float* __restrict__ out, int out_size) {
    __shared__ __align__(16) int skey[NBINS];
    __shared__ u64 cand[NWORDS];
    __shared__ u64 kept[NWORDS];
    __shared__ int cur_i;
    __shared__ unsigned int is_last;
    int tid = threadIdx.x;

    // reset K1's grid-barrier counters for the next replay
    if (blockIdx.x == 0 && tid < 4) g_bar[tid] = 0;

    for (int l = tid; l < NBINS; l += 1024) {
        int cnt = (int)(g_acc2[l] & 0xFFFFFFFFULL);
        int s = (cnt >= 10) ? cnt : -1;
        skey[l] = ((s + 1) << 12) | (NBINS - 1 - l);
    }
    __syncthreads();

    int w = tid >> 5;                  // warp = key within block (0..31)
    int lane = tid & 31;
    int i = blockIdx.x * 32 + w;
    int ki = skey[i];
    const int4* k4 = (const int4*)skey;
    int r = 0;
    #pragma unroll 8
    for (int n = 0; n < 32; n++) {
        int4 v = k4[n * 32 + lane];
        r += (v.x > ki) + (v.y > ki) + (v.z > ki) + (v.w > ki);
    }
    #pragma unroll
    for (int d = 1; d < 32; d <<= 1)
        r += __shfl_xor_sync(0xFFFFFFFFu, r, d);

    if (lane == 0) {
        u64 a1 = g_acc1[i];
        u64 a2 = g_acc2[i];
        int cnt = (int)(a2 & 0xFFFFFFFFULL);
        int sx = (int)(a1 >> 32) - 256 * cnt;
        int sy = (int)(a1 & 0xFFFFFFFFULL) - 256 * cnt;
        int sz = (int)(a2 >> 32) - 256 * cnt;
        float d = fmaxf((float)cnt, 1.0f);
        float c0 = (float)sx / d;
        float c1 = (float)sy / d;
        float c2 = (float)sz / d;
        if (i * 3 + 2 < out_size) {
            out[i * 3 + 0] = c0;
            out[i * 3 + 1] = c1;
            out[i * 3 + 2] = c2;
        }
        float4 bx;
        bx.x = c0 - 22.5f;
        bx.y = c1 - 22.5f;
        bx.z = c0 + 22.5f;
        bx.w = c1 + 22.5f;
        g_order[r] = i;
        g_bsort[r] = bx;
        if (cnt >= 10)  // is_cluster
            atomicOr(&g_clusterbits[r >> 6], 1ULL << (r & 63));
    }

    // ---- completion detection: last block runs NMS --------------------------
    __threadfence();
    __syncthreads();
    if (tid == 0)
        is_last = (atomicAdd(&g_done, 1u) == gridDim.x - 1) ? 1u : 0u;
    __syncthreads();
    if (!is_last) return;
    if (tid == 0) g_done = 0;          // reset for next replay

    // ---- greedy NMS: 1024 threads, 4 sorted boxes per thread ----------------
    if (tid < NWORDS) { cand[tid] = g_clusterbits[tid]; kept[tid] = 0ULL; }

    float4 bj[4];
    float a2v[4];
    #pragma unroll
    for (int k = 0; k < 4; k++) {
        bj[k] = g_bsort[tid * 4 + k];
        a2v[k] = (bj[k].z - bj[k].x) * (bj[k].w - bj[k].y);
    }

    while (true) {
        __syncthreads();
        if (tid == 0) {
            int found = -1;
            for (int ww = 0; ww < NWORDS; ww++) {
                u64 cw = cand[ww];
                if (cw) { found = (ww << 6) + __ffsll((long long)cw) - 1; break; }
            }
            cur_i = found;
            if (found >= 0) {
                kept[found >> 6] |= 1ULL << (found & 63);
                cand[found >> 6] &= ~(1ULL << (found & 63));
            }
        }
        __syncthreads();
        int ii = cur_i;
        if (ii < 0) break;
        float4 bi = g_bsort[ii];
        float a1 = (bi.z - bi.x) * (bi.w - bi.y);
        unsigned int sup4 = 0;
        #pragma unroll
        for (int k = 0; k < 4; k++) {
            int j = tid * 4 + k;
            float xx1 = fmaxf(bi.x, bj[k].x);
            float yy1 = fmaxf(bi.y, bj[k].y);
            float xx2 = fminf(bi.z, bj[k].z);
            float yy2 = fminf(bi.w, bj[k].w);
            float inter = fmaxf(xx2 - xx1, 0.0f) * fmaxf(yy2 - yy1, 0.0f);
            float iou = inter / fmaxf(a1 + a2v[k] - inter, 1e-9f);
            if (j > ii && iou > 0.5f) sup4 |= 1u << k;
        }
        if (sup4)
            atomicAnd(&cand[tid >> 4],
                      ~((u64)sup4 << ((tid & 15) * 4)));
    }

    __syncthreads();
    #pragma unroll
    for (int k = 0; k < 4; k++) {
        int rr = tid * 4 + k;
        float v = (float)((kept[rr >> 6] >> (rr & 63)) & 1ULL);
        int pos = 3 * NBINS + g_order[rr];
        if (pos < out_size) out[pos] = v;
    }
}

// ============================================================================
extern "C" void kernel_launch(void* const* d_in, const int* in_sizes, int n_in,
                              void* d_out, int out_size) {
    const float* emb = (const float*)d_in[0];   // (1,3,512,512,48) float32
    const float* pm  = (const float*)d_in[1];   // (1,1,512,512,48) float32
    float* out = (float*)d_out;

    static int sms = 0;
    if (sms == 0) cudaDeviceGetAttribute(&sms, cudaDevAttrMultiProcessorCount, 0);

    mega_kernel<<<sms, 1024>>>(emb, pm);
    rank_nms_kernel<<<128, 1024>>>(out, out_size);
}

// round 7
// speedup vs baseline: 2.2154x; 1.0498x over previous
#include <cuda_runtime.h>

// ============================================================================
// EstimateCentroids, 2 kernels:
//  K1 (persistent, grid = #SMs, software grid barriers):
//     A: binarize + z-erosion (bit-packed)            -> g_zbits
//     B: y- then x-erosion (shared tiles)             -> g_xbits
//     C: hash-binned packed-u64 shared-atomic sums    -> g_acc*  (2x unroll)
//     D: packed-key stable rank sort + scatter (ldcg) -> g_bsort/g_order/bits
//  K2: greedy NMS (1 block) + keep output; resets K1's barrier counters.
// ============================================================================

#define XD 512
#define YD 512
#define ZD 48
#define NROWS (XD * YD)              // 262144
#define NVOX  (NROWS * ZD)           // 12582912
#define NQUADS (NVOX / 4)            // 3145728
#define NCHUNKS (NQUADS / 3072)      // 1024
#define NBINS 4096
#define NWORDS 64

typedef unsigned long long u64;

// ---------------- device scratch (static: no allocations allowed) -----------
__device__ u64 g_zbits[NROWS];
__device__ u64 g_xbits[NROWS];
__device__ u64 g_acc1[NBINS];        // (sx+256c)<<32 | (sy+256c)
__device__ u64 g_acc2[NBINS];        // (sz+256c)<<32 | c
__device__ float4 g_bsort[NBINS];
__device__ int    g_order[NBINS];
__device__ u64 g_clusterbits[NWORDS];
__device__ unsigned int g_bar[4];    // grid-barrier counters (reset by K2)

// ---------------- software grid barrier (all blocks resident) ---------------
__device__ __forceinline__ void grid_bar(int phase) {
    __threadfence();                  // each thread flushes its own writes
    __syncthreads();
    if (threadIdx.x == 0) {
        atomicAdd(&g_bar[phase], 1u);
        while (*(volatile unsigned int*)&g_bar[phase] < gridDim.x) { }
    }
    __syncthreads();
}

// ---------------- phase C per-voxel helper ----------------------------------
__device__ __forceinline__ void accum_quad(u64* sbins, unsigned int m4,
                                           float4 fa, float4 fb, float4 fc) {
    float ax[4]  = {fa.x, fa.y, fa.z, fa.w};
    float bx[4]  = {fb.x, fb.y, fb.z, fb.w};
    float cx4[4] = {fc.x, fc.y, fc.z, fc.w};
    #pragma unroll
    for (int k = 0; k < 4; k++) {
        if (!((m4 >> k) & 1u)) continue;
        float a = ax[k], b = bx[k], c2 = cx4[k];
        if (a > -2.0f || b > -2.0f || c2 > -2.0f) {
            int cx = __float2int_rn(a * 25.0f);   // round-half-even == jnp.round
            int cy = __float2int_rn(b * 25.0f);
            int cz = __float2int_rn(c2 * 25.0f);
            unsigned int qx = (unsigned int)min(max(cx + 128, 0), 255);
            unsigned int qy = (unsigned int)min(max(cy + 128, 0), 255);
            unsigned int qz = (unsigned int)min(max(cz + 128, 0), 255);
            unsigned int h = qx * 73856093u ^ qy * 19349663u ^ qz * 83492791u;
            unsigned int seg = h & (NBINS - 1);
            u64 p = (1ULL << 48) |
                    ((u64)(unsigned int)(cx + 256) << 32) |
                    ((u64)(unsigned int)(cy + 256) << 16) |
                    (u64)(unsigned int)(cz + 256);
            atomicAdd(&sbins[seg], p);
        }
    }
}

// ============================================================================
// K1: erode_z -> erode_yx -> accumulate -> rank+scatter (one persistent kernel)
// ============================================================================
__global__ void __launch_bounds__(1024, 1) mega_kernel(const float* __restrict__ emb,
                                                       const float* __restrict__ pm,
                                                       float* __restrict__ out,
                                                       int out_size) {
    __shared__ __align__(16) unsigned char smem_raw[32768];
    int tid = threadIdx.x;

    // -------- phase A: binarize + z-erosion, 3072 quads (256 rows) per chunk
    {
        unsigned char* nib = smem_raw;
        const float4* pm4 = (const float4*)pm;
        for (int c = blockIdx.x; c < NCHUNKS; c += gridDim.x) {
            __syncthreads();          // protect nib reuse across chunks
            #pragma unroll
            for (int r = 0; r < 3; r++) {
                float4 v = pm4[c * 3072 + r * 1024 + tid];
                unsigned int n = (v.x > 0.5f ? 1u : 0u) | (v.y > 0.5f ? 2u : 0u) |
                                 (v.z > 0.5f ? 4u : 0u) | (v.w > 0.5f ? 8u : 0u);
                nib[r * 1024 + tid] = (unsigned char)n;
            }
            __syncthreads();
            if (tid < 256) {
                u64 b = 0ULL;
                #pragma unroll
                for (int k = 0; k < 12; k++)
                    b |= (u64)nib[tid * 12 + k] << (4 * k);
                u64 e = b;
                #pragma unroll
                for (int k = 1; k <= 4; k++)
                    e &= (b >> k) & (b << k);
                e &= 0x0000FFFFFFFFFFFFULL;
                g_zbits[c * 256 + tid] = e;
            }
        }
        // fused zeroing of accumulator arrays (done before barrier 0)
        if (blockIdx.x == 0) {
            for (int l = tid; l < NBINS; l += 1024) { g_acc1[l] = 0ULL; g_acc2[l] = 0ULL; }
            if (tid < NWORDS) g_clusterbits[tid] = 0ULL;
        }
    }
    grid_bar(0);

    // -------- phase B: y then x erosion, 32x32-row tiles with 4-halo --------
    {
        u64* szt = (u64*)smem_raw;                     // [40*40]
        u64* syt = (u64*)(smem_raw + 12800);           // [40*32]
        for (int t = blockIdx.x; t < 256; t += gridDim.x) {
            __syncthreads();
            int x0 = (t >> 4) * 32, y0 = (t & 15) * 32;
            for (int l = tid; l < 1600; l += 1024) {
                int xx = l / 40, yy = l - xx * 40;
                int gx = x0 + xx - 4, gy = y0 + yy - 4;
                u64 v = 0ULL;
                if (gx >= 0 && gx < XD && gy >= 0 && gy < YD)
                    v = g_zbits[gx * YD + gy];
                szt[xx * 40 + yy] = v;
            }
            __syncthreads();
            for (int l = tid; l < 1280; l += 1024) {
                int xx = l >> 5, yy = l & 31;
                int gy = y0 + yy;
                u64 r = 0ULL;
                if (gy >= 4 && gy <= YD - 5) {
                    r = ~0ULL;
                    #pragma unroll
                    for (int dy = 0; dy <= 8; dy++)
                        r &= szt[xx * 40 + yy + dy];
                }
                syt[xx * 32 + yy] = r;
            }
            __syncthreads();
            {
                int xx = tid >> 5, yy = tid & 31;
                int gx = x0 + xx;
                u64 r = 0ULL;
                if (gx >= 4 && gx <= XD - 5) {
                    r = ~0ULL;
                    #pragma unroll
                    for (int dx = 0; dx <= 8; dx++)
                        r &= syt[(xx + dx) * 32 + yy];
                }
                g_xbits[gx * YD + (y0 + yy)] = r;
            }
        }
    }
    grid_bar(1);

    // -------- phase C: hash-binned packed accumulation (2x unrolled) --------
    {
        u64* sbins = (u64*)smem_raw;
        for (int i = tid; i < NBINS; i += 1024) sbins[i] = 0ULL;
        __syncthreads();

        const float4* __restrict__ p0 = (const float4*)emb;
        const float4* __restrict__ p1 = (const float4*)(emb + NVOX);
        const float4* __restrict__ p2 = (const float4*)(emb + 2 * NVOX);

        int stride = gridDim.x * 1024;
        for (int q = blockIdx.x * 1024 + tid; q < NQUADS; q += 2 * stride) {
            int q2 = q + stride;
            bool ok2 = q2 < NQUADS;
            unsigned int rowa = (unsigned int)q / 12u;
            unsigned int zca = (unsigned int)q - rowa * 12u;
            unsigned int m4a = (unsigned int)(g_xbits[rowa] >> (zca * 4)) & 0xFu;
            unsigned int m4b = 0;
            if (ok2) {
                unsigned int rowb = (unsigned int)q2 / 12u;
                unsigned int zcb = (unsigned int)q2 - rowb * 12u;
                m4b = (unsigned int)(g_xbits[rowb] >> (zcb * 4)) & 0xFu;
            }
            float4 A0, A1, A2, B0, B1, B2;
            if (m4a) { A0 = p0[q];  A1 = p1[q];  A2 = p2[q];  }
            if (m4b) { B0 = p0[q2]; B1 = p1[q2]; B2 = p2[q2]; }
            if (m4a) accum_quad(sbins, m4a, A0, A1, A2);
            if (m4b) accum_quad(sbins, m4b, B0, B1, B2);
        }
        __syncthreads();

        for (int i = tid; i < NBINS; i += 1024) {
            u64 p = sbins[i];
            if (p) {
                u64 cnt = p >> 48;
                u64 xf = (p >> 32) & 0xFFFFULL;
                u64 yf = (p >> 16) & 0xFFFFULL;
                u64 zf = p & 0xFFFFULL;
                atomicAdd(&g_acc1[i], (xf << 32) | yf);
                atomicAdd(&g_acc2[i], (zf << 32) | cnt);
            }
        }
    }
    grid_bar(2);

    // -------- phase D: packed-key stable rank sort + scatter -----------------
    // Key k_j = ((s_j+1)<<12) | (4095-j): k_j > k_i <=> (s_j>s_i) or
    // (s_j==s_i && j<i), so rank(i) = #{j : k_j > k_i} == argsort(-s) rank.
    // NOTE: g_acc* must be read with __ldcg — block 0's L1 holds the stale
    // zeroed lines from phase A (phase C atomics only updated L2).
    {
        int* skey = (int*)smem_raw;
        for (int l = tid; l < NBINS; l += 1024) {
            int cnt = (int)(__ldcg(&g_acc2[l]) & 0xFFFFFFFFULL);
            int s = (cnt >= 10) ? cnt : -1;
            skey[l] = ((s + 1) << 12) | (NBINS - 1 - l);
        }
        __syncthreads();

        int w = tid >> 5;
        int lane = tid & 31;
        const int4* k4 = (const int4*)skey;
        for (int kb = blockIdx.x; kb < 128; kb += gridDim.x) {
            int i = kb * 32 + w;
            int ki = skey[i];
            int r = 0;
            #pragma unroll 8
            for (int n = 0; n < 32; n++) {
                int4 v = k4[n * 32 + lane];
                r += (v.x > ki) + (v.y > ki) + (v.z > ki) + (v.w > ki);
            }
            #pragma unroll
            for (int d = 1; d < 32; d <<= 1)
                r += __shfl_xor_sync(0xFFFFFFFFu, r, d);

            if (lane == 0) {
                u64 a1 = __ldcg(&g_acc1[i]);
                u64 a2 = __ldcg(&g_acc2[i]);
                int cnt = (int)(a2 & 0xFFFFFFFFULL);
                int sx = (int)(a1 >> 32) - 256 * cnt;
                int sy = (int)(a1 & 0xFFFFFFFFULL) - 256 * cnt;
                int sz = (int)(a2 >> 32) - 256 * cnt;
                float d = fmaxf((float)cnt, 1.0f);
                float c0 = (float)sx / d;
                float c1 = (float)sy / d;
                float c2 = (float)sz / d;
                if (i * 3 + 2 < out_size) {
                    out[i * 3 + 0] = c0;
                    out[i * 3 + 1] = c1;
                    out[i * 3 + 2] = c2;
                }
                float4 bx;
                bx.x = c0 - 22.5f;
                bx.y = c1 - 22.5f;
                bx.z = c0 + 22.5f;
                bx.w = c1 + 22.5f;
                g_order[r] = i;
                g_bsort[r] = bx;
                if (cnt >= 10)  // is_cluster
                    atomicOr(&g_clusterbits[r >> 6], 1ULL << (r & 63));
            }
        }
    }
}

// ============================================================================
// K2: greedy NMS (single block, 1024 threads, 4 sorted boxes per thread) +
// keep output. Also resets K1's grid-barrier counters (safe: this launch is
// serialized after all K1 blocks have exited).
// Exact reference semantics: iterate candidates in sorted order; a kept box
// suppresses all later boxes with IOU > 0.5.
// ============================================================================
__global__ void __launch_bounds__(1024) nms_kernel(float* __restrict__ out, int out_size) {
    __shared__ u64 cand[NWORDS];
    __shared__ u64 kept[NWORDS];
    __shared__ int cur_i;
    int tid = threadIdx.x;

    if (tid < 4) g_bar[tid] = 0;      // reset for next replay
    if (tid < NWORDS) { cand[tid] = g_clusterbits[tid]; kept[tid] = 0ULL; }

    float4 bj[4];
    float a2v[4];
    #pragma unroll
    for (int k = 0; k < 4; k++) {
        bj[k] = g_bsort[tid * 4 + k];
        a2v[k] = (bj[k].z - bj[k].x) * (bj[k].w - bj[k].y);
    }
    __syncthreads();

    while (true) {
        if (tid == 0) {
            int found = -1;
            for (int ww = 0; ww < NWORDS; ww++) {
                u64 cw = cand[ww];
                if (cw) { found = (ww << 6) + __ffsll((long long)cw) - 1; break; }
            }
            cur_i = found;
            if (found >= 0) {
                kept[found >> 6] |= 1ULL << (found & 63);
                cand[found >> 6] &= ~(1ULL << (found & 63));
            }
        }
        __syncthreads();
        int ii = cur_i;
        if (ii < 0) break;
        float4 bi = g_bsort[ii];
        float a1 = (bi.z - bi.x) * (bi.w - bi.y);
        unsigned int sup4 = 0;
        #pragma unroll
        for (int k = 0; k < 4; k++) {
            int j = tid * 4 + k;
            float xx1 = fmaxf(bi.x, bj[k].x);
            float yy1 = fmaxf(bi.y, bj[k].y);
            float xx2 = fminf(bi.z, bj[k].z);
            float yy2 = fminf(bi.w, bj[k].w);
            float inter = fmaxf(xx2 - xx1, 0.0f) * fmaxf(yy2 - yy1, 0.0f);
            float iou = inter / fmaxf(a1 + a2v[k] - inter, 1e-9f);
            if (j > ii && iou > 0.5f) sup4 |= 1u << k;
        }
        if (sup4)
            atomicAnd(&cand[tid >> 4],
                      ~((u64)sup4 << ((tid & 15) * 4)));
        __syncthreads();
    }

    #pragma unroll
    for (int k = 0; k < 4; k++) {
        int rr = tid * 4 + k;
        float v = (float)((kept[rr >> 6] >> (rr & 63)) & 1ULL);
        int pos = 3 * NBINS + g_order[rr];
        if (pos < out_size) out[pos] = v;
    }
}

// ============================================================================
extern "C" void kernel_launch(void* const* d_in, const int* in_sizes, int n_in,
                              void* d_out, int out_size) {
    const float* emb = (const float*)d_in[0];   // (1,3,512,512,48) float32
    const float* pm  = (const float*)d_in[1];   // (1,1,512,512,48) float32
    float* out = (float*)d_out;

    static int sms = 0;
    if (sms == 0) cudaDeviceGetAttribute(&sms, cudaDevAttrMultiProcessorCount, 0);

    mega_kernel<<<sms, 1024>>>(emb, pm, out, out_size);
    nms_kernel<<<1, 1024>>>(out, out_size);
}